// round 1
// baseline (speedup 1.0000x reference)
#include <cuda_runtime.h>
#include <cuda_bf16.h>
#include <math.h>

// ---------------- problem constants ----------------
#define BB      4
#define LL      4096
#define DMODEL  1024
#define DINNER  2048
#define NHEADS  16
#define HDIM    128
#define DSTATE  64
#define PROJ    4256
#define MROWS   (BB*LL)          // 16384

// ---------------- scratch (__device__ globals; no runtime alloc) -------------
__device__ __align__(16) float g_xin  [(size_t)MROWS * DMODEL];
__device__ __align__(16) float g_proj [(size_t)MROWS * PROJ];
__device__ __align__(16) float g_xs   [(size_t)MROWS * DINNER];
__device__ __align__(16) float g_yfull[(size_t)MROWS * DINNER];
__device__ __align__(16) float g_yz   [(size_t)MROWS * DINNER];
__device__ __align__(16) float g_Bc   [(size_t)MROWS * DSTATE];
__device__ __align__(16) float g_Cc   [(size_t)MROWS * DSTATE];
__device__ __align__(16) float g_coef [(size_t)MROWS * NHEADS * 4];
__device__ __align__(16) float g_theta[(size_t)MROWS * 32];
__device__ __align__(16) float g_phi  [(size_t)MROWS * 32];
__device__ __align__(16) float g_csum [(size_t)BB * 64 * 32];

// ---------------- layernorm + theta (fused, one block per row) ---------------
__global__ void __launch_bounds__(256) k_ln_theta(const float* __restrict__ u,
        const float* __restrict__ gscale, const float* __restrict__ gbias,
        const float* __restrict__ tw)
{
    __shared__ float su[1024];
    __shared__ float rsum[8], rsq[8];
    __shared__ float s_mu, s_rs;
    __shared__ float sth[8][32];
    int m = blockIdx.x, tid = threadIdx.x;
    const float* ur = u + (size_t)m * 1024 + tid * 4;
    float4 v = *(const float4*)ur;
    *(float4*)(su + tid * 4) = v;
    float s = v.x + v.y + v.z + v.w;
    float q = v.x*v.x + v.y*v.y + v.z*v.z + v.w*v.w;
    #pragma unroll
    for (int o = 16; o; o >>= 1) {
        s += __shfl_xor_sync(0xffffffffu, s, o);
        q += __shfl_xor_sync(0xffffffffu, q, o);
    }
    int lane = tid & 31, wid = tid >> 5;
    if (lane == 0) { rsum[wid] = s; rsq[wid] = q; }
    __syncthreads();
    if (tid == 0) {
        float S = 0.f, Q = 0.f;
        #pragma unroll
        for (int i = 0; i < 8; i++) { S += rsum[i]; Q += rsq[i]; }
        float mu  = S * (1.f / 1024.f);
        float var = Q * (1.f / 1024.f) - mu * mu;
        s_mu = mu;
        s_rs = rsqrtf(var + 1e-6f);
    }
    __syncthreads();
    float mu = s_mu, rs = s_rs;
    float4 sc = *(const float4*)(gscale + tid * 4);
    float4 bi = *(const float4*)(gbias  + tid * 4);
    float4 o;
    o.x = (v.x - mu) * rs * sc.x + bi.x;
    o.y = (v.y - mu) * rs * sc.y + bi.y;
    o.z = (v.z - mu) * rs * sc.z + bi.z;
    o.w = (v.w - mu) * rs * sc.w + bi.w;
    *(float4*)(g_xin + (size_t)m * 1024 + tid * 4) = o;

    // theta = u_row @ theta_w  (32 cols), u row is in shared
    int c = tid & 31, kc = tid >> 5;
    float acc = 0.f;
    const float* twp = tw + kc * 128 * 32 + c;
    const float* sup = su + kc * 128;
    #pragma unroll 8
    for (int kk = 0; kk < 128; ++kk) acc = fmaf(sup[kk], twp[kk * 32], acc);
    sth[kc][c] = acc;
    __syncthreads();
    if (tid < 32) {
        float t2 = 0.f;
        #pragma unroll
        for (int i = 0; i < 8; i++) t2 += sth[i][tid];
        g_theta[(size_t)m * 32 + tid] = t2;
    }
}

// ---------------- SIMT sgemm: 128x128 block tile, BK=8, 8x8/thread ----------
template<bool WITH_ADD>
__global__ void __launch_bounds__(256) k_sgemm(const float* __restrict__ A,
        const float* __restrict__ B, const float* __restrict__ ADD,
        float* __restrict__ C, int M, int N, int K)
{
    __shared__ float As[2][8][128];
    __shared__ float Bs[2][8][128];
    int tid = threadIdx.x;
    int n0 = blockIdx.x * 128, m0 = blockIdx.y * 128;

    int ar = tid >> 1, ac = (tid & 1) * 4;
    const float* Aptr = A + (size_t)(m0 + ar) * K + ac;
    int bcol = (tid & 31) * 4;
    int brow = tid >> 5;
    const float* Bptr = B + (size_t)brow * N + n0 + bcol;
    bool bval = (n0 + bcol) < N;

    float4 a4 = *(const float4*)Aptr;
    float4 b4 = bval ? *(const float4*)Bptr : make_float4(0.f, 0.f, 0.f, 0.f);
    As[0][ac + 0][ar] = a4.x; As[0][ac + 1][ar] = a4.y;
    As[0][ac + 2][ar] = a4.z; As[0][ac + 3][ar] = a4.w;
    *(float4*)&Bs[0][brow][bcol] = b4;
    __syncthreads();

    float acc[8][8];
    #pragma unroll
    for (int i = 0; i < 8; i++)
        #pragma unroll
        for (int j = 0; j < 8; j++) acc[i][j] = 0.f;

    int ty = tid >> 4, tx = tid & 15;
    int KT = K >> 3;
    int buf = 0;
    for (int kt = 0; kt < KT; ++kt) {
        float4 na4 = a4, nb4 = b4;
        if (kt + 1 < KT) {
            Aptr += 8; Bptr += (size_t)8 * N;
            na4 = *(const float4*)Aptr;
            nb4 = bval ? *(const float4*)Bptr : make_float4(0.f, 0.f, 0.f, 0.f);
        }
        #pragma unroll
        for (int k = 0; k < 8; k++) {
            float4 a0 = *(const float4*)&As[buf][k][ty * 4];
            float4 a1 = *(const float4*)&As[buf][k][64 + ty * 4];
            float4 bb0 = *(const float4*)&Bs[buf][k][tx * 4];
            float4 bb1 = *(const float4*)&Bs[buf][k][64 + tx * 4];
            float ar8[8] = {a0.x, a0.y, a0.z, a0.w, a1.x, a1.y, a1.z, a1.w};
            float br8[8] = {bb0.x, bb0.y, bb0.z, bb0.w, bb1.x, bb1.y, bb1.z, bb1.w};
            #pragma unroll
            for (int i = 0; i < 8; i++)
                #pragma unroll
                for (int j = 0; j < 8; j++)
                    acc[i][j] = fmaf(ar8[i], br8[j], acc[i][j]);
        }
        if (kt + 1 < KT) {
            buf ^= 1;
            As[buf][ac + 0][ar] = na4.x; As[buf][ac + 1][ar] = na4.y;
            As[buf][ac + 2][ar] = na4.z; As[buf][ac + 3][ar] = na4.w;
            *(float4*)&Bs[buf][brow][bcol] = nb4;
            __syncthreads();
        }
    }

    #pragma unroll
    for (int i = 0; i < 8; i++) {
        int row = m0 + ((i < 4) ? (ty * 4 + i) : (64 + ty * 4 + (i - 4)));
        #pragma unroll
        for (int jh = 0; jh < 2; jh++) {
            int col = n0 + jh * 64 + tx * 4;
            if (col < N) {
                float4 v;
                v.x = acc[i][jh * 4 + 0]; v.y = acc[i][jh * 4 + 1];
                v.z = acc[i][jh * 4 + 2]; v.w = acc[i][jh * 4 + 3];
                if (WITH_ADD) {
                    float4 av = *(const float4*)(ADD + (size_t)row * N + col);
                    v.x += av.x; v.y += av.y; v.z += av.z; v.w += av.w;
                }
                *(float4*)(C + (size_t)row * N + col) = v;
            }
        }
    }
}

// ---------------- per-row prep: silu(x), rmsnorm(B/C), dt/lam coefs, dphi ----
__global__ void __launch_bounds__(256) k_prep(const float* __restrict__ A_log,
        const float* __restrict__ dt_bias,
        const float* __restrict__ bcB, const float* __restrict__ bcC,
        const float* __restrict__ Bbias, const float* __restrict__ Cbias)
{
    int m = blockIdx.x, tid = threadIdx.x;
    const float* row = g_proj + (size_t)m * PROJ;
    __shared__ float s_dts;

    // silu(x) -> g_xs
    #pragma unroll
    for (int it = 0; it < 2; ++it) {
        int j4 = tid + it * 256;
        float4 v = *(const float4*)(row + j4 * 4);
        float4 o;
        o.x = v.x / (1.f + expf(-v.x));
        o.y = v.y / (1.f + expf(-v.y));
        o.z = v.z / (1.f + expf(-v.z));
        o.w = v.w / (1.f + expf(-v.w));
        *(float4*)(g_xs + (size_t)m * DINNER + j4 * 4) = o;
    }

    int lane = tid & 31, wid = tid >> 5;
    if (wid == 0) {                       // rmsnorm(B_raw)
        float b0 = row[4096 + lane], b1 = row[4128 + lane];
        float ss = b0 * b0 + b1 * b1;
        #pragma unroll
        for (int o = 16; o; o >>= 1) ss += __shfl_xor_sync(0xffffffffu, ss, o);
        float r = rsqrtf(ss * (1.f / 64.f) + 1e-6f);
        g_Bc[(size_t)m * 64 + lane]      = b0 * r * bcB[lane]      + Bbias[lane];
        g_Bc[(size_t)m * 64 + 32 + lane] = b1 * r * bcB[32 + lane] + Bbias[32 + lane];
    } else if (wid == 1) {                // rmsnorm(C_raw)
        float b0 = row[4160 + lane], b1 = row[4192 + lane];
        float ss = b0 * b0 + b1 * b1;
        #pragma unroll
        for (int o = 16; o; o >>= 1) ss += __shfl_xor_sync(0xffffffffu, ss, o);
        float r = rsqrtf(ss * (1.f / 64.f) + 1e-6f);
        g_Cc[(size_t)m * 64 + lane]      = b0 * r * bcC[lane]      + Cbias[lane];
        g_Cc[(size_t)m * 64 + 32 + lane] = b1 * r * bcC[32 + lane] + Cbias[32 + lane];
    } else if (wid == 2) {                // dt / lam / recurrence coefs
        float dt = 0.f;
        if (lane < 16) {
            float x = row[4224 + lane] + dt_bias[lane];
            dt = (x > 20.f) ? x : log1pf(expf(x));
            float lamr = row[4240 + lane];
            float lam = 1.f / (1.f + expf(-lamr));
            float a = expf(-expf(A_log[lane]) * dt);
            size_t o = ((size_t)m * 16 + lane) * 4;
            g_coef[o]     = a;
            g_coef[o + 1] = dt * lam;
            g_coef[o + 2] = dt * (1.f - lam) * a;
            g_coef[o + 3] = 0.f;
        }
        float s = dt;
        #pragma unroll
        for (int o = 16; o; o >>= 1) s += __shfl_xor_sync(0xffffffffu, s, o);
        if (lane == 0) s_dts = s * (1.f / 16.f);
    }
    __syncthreads();
    if (tid < 32)
        g_phi[(size_t)m * 32 + tid] = s_dts * g_theta[(size_t)m * 32 + tid];
}

// ---------------- 3-phase cumsum of g_phi over L (per batch, per col) -------
__global__ void k_cs_chunk()   // grid 256 (b*64+ch), 32 threads
{
    int b = blockIdx.x >> 6, ch = blockIdx.x & 63;
    int c = threadIdx.x;
    size_t base = (((size_t)b * 4096) + (size_t)ch * 64) * 32 + c;
    float acc = 0.f;
    #pragma unroll 8
    for (int l = 0; l < 64; ++l) {
        acc += g_phi[base + (size_t)l * 32];
        g_phi[base + (size_t)l * 32] = acc;
    }
    g_csum[((size_t)(b * 64 + ch)) * 32 + c] = acc;
}
__global__ void k_cs_scan()    // 1 block, 128 threads
{
    int tid = threadIdx.x;
    int b = tid >> 5, c = tid & 31;
    float acc = 0.f;
    for (int ch = 0; ch < 64; ++ch) {
        size_t o = ((size_t)(b * 64 + ch)) * 32 + c;
        float t = g_csum[o];
        g_csum[o] = acc;
        acc += t;
    }
}
__global__ void k_cs_add()     // grid 256 (b*64+ch), 256 threads
{
    int b = blockIdx.x >> 6, ch = blockIdx.x & 63;
    __shared__ float off[32];
    if (threadIdx.x < 32)
        off[threadIdx.x] = g_csum[((size_t)(b * 64 + ch)) * 32 + threadIdx.x];
    __syncthreads();
    size_t base = (((size_t)b * 4096) + (size_t)ch * 64) * 32;
    for (int e = threadIdx.x; e < 2048; e += 256)
        g_phi[base + e] += off[e & 31];
}

// ---------------- RoPE on B_ssm / C_ssm (in place) ---------------------------
__global__ void k_rope()       // grid 2048, 256 threads (8 rows/block)
{
    int tid = threadIdx.x;
    int r = tid >> 5, lane = tid & 31;
    size_t m = (size_t)blockIdx.x * 8 + r;
    float ph = g_phi[m * 32 + lane];
    float cc = cosf(ph), ss = sinf(ph);
    size_t o = m * 64 + lane;
    float xr = g_Bc[o], xi = g_Bc[o + 32];
    g_Bc[o]      = xr * cc - xi * ss;
    g_Bc[o + 32] = xr * ss + xi * cc;
    xr = g_Cc[o]; xi = g_Cc[o + 32];
    g_Cc[o]      = xr * cc - xi * ss;
    g_Cc[o + 32] = xr * ss + xi * cc;
}

// ---------------- SSD trapezoidal scan ---------------------------------------
// grid 256 = (b:4, h:16, pg:4); 256 threads: thread = (p_local 0..31, nsub 0..7)
// each thread owns h[p, nsub*8 .. nsub*8+8) in registers.
__global__ void __launch_bounds__(256) k_scan(const float* __restrict__ Dv)
{
    int bx = blockIdx.x;
    int pg = bx & 3, h = (bx >> 2) & 15, b = bx >> 6;
    int tid = threadIdx.x;
    int nsub = tid & 7, pl = tid >> 3;
    int p = pg * 32 + pl;
    size_t mb = (size_t)b * 4096;
    const float* Bp = g_Bc + mb * 64 + nsub * 8;
    const float* Cp = g_Cc + mb * 64 + nsub * 8;
    const float* Kp = g_coef + (mb * 16 + h) * 4;
    const float* Xp = g_xs + mb * 2048 + h * 128 + p;
    float*       Yp = g_yfull + mb * 2048 + h * 128 + p;
    float Dh = Dv[h];

    float hs[8], Bprev[8];
    #pragma unroll
    for (int i = 0; i < 8; i++) { hs[i] = 0.f; Bprev[i] = 0.f; }
    float xprev = 0.f;

    float4 b0 = *(const float4*)Bp;
    float4 b1 = *(const float4*)(Bp + 4);
    float4 c0 = *(const float4*)Cp;
    float4 c1 = *(const float4*)(Cp + 4);
    float4 cf = *(const float4*)Kp;
    float  xc = *Xp;

    for (int t = 0; t < 4096; ++t) {
        float4 nb0 = b0, nb1 = b1, nc0 = c0, nc1 = c1, ncf = cf;
        float nx = xc;
        if (t < 4095) {                      // prefetch next timestep
            Bp += 64; Cp += 64; Kp += 64; Xp += 2048;
            nb0 = *(const float4*)Bp; nb1 = *(const float4*)(Bp + 4);
            nc0 = *(const float4*)Cp; nc1 = *(const float4*)(Cp + 4);
            ncf = *(const float4*)Kp; nx = *Xp;
        }
        float ca  = cf.x;
        float c1x = cf.y * xc;
        float c2x = cf.z * xprev;
        float Bn[8] = {b0.x, b0.y, b0.z, b0.w, b1.x, b1.y, b1.z, b1.w};
        float Cn[8] = {c0.x, c0.y, c0.z, c0.w, c1.x, c1.y, c1.z, c1.w};
        float acc = 0.f;
        #pragma unroll
        for (int i = 0; i < 8; i++) {
            float bx_ = fmaf(c1x, Bn[i], c2x * Bprev[i]);
            hs[i] = fmaf(ca, hs[i], bx_);
            acc = fmaf(hs[i], Cn[i], acc);
            Bprev[i] = Bn[i];
        }
        xprev = xc;
        acc += __shfl_xor_sync(0xffffffffu, acc, 1);
        acc += __shfl_xor_sync(0xffffffffu, acc, 2);
        acc += __shfl_xor_sync(0xffffffffu, acc, 4);
        if (nsub == 0) *Yp = fmaf(Dh, xc, acc);
        Yp += 2048;
        b0 = nb0; b1 = nb1; c0 = nc0; c1 = nc1; cf = ncf; xc = nx;
    }
}

// ---------------- yz = y_full * silu(z) --------------------------------------
__global__ void k_mul()        // grid 32768, 256 threads, 1 float4/thread
{
    size_t f4 = (size_t)blockIdx.x * 256 + threadIdx.x;
    size_t flat = f4 * 4;
    size_t m = flat >> 11;
    int j = (int)(flat & 2047);
    float4 y = *(const float4*)(g_yfull + flat);
    float4 z = *(const float4*)(g_proj + m * PROJ + 2048 + j);
    float4 o;
    o.x = y.x * (z.x / (1.f + expf(-z.x)));
    o.y = y.y * (z.y / (1.f + expf(-z.y)));
    o.z = y.z * (z.z / (1.f + expf(-z.z)));
    o.w = y.w * (z.w / (1.f + expf(-z.w)));
    *(float4*)(g_yz + flat) = o;
}

// ---------------- host launcher ----------------------------------------------
static float* sym_addr(const void* s)
{
    void* p = nullptr;
    cudaGetSymbolAddress(&p, s);
    return (float*)p;
}

extern "C" void kernel_launch(void* const* d_in, const int* in_sizes, int n_in,
                              void* d_out, int out_size)
{
    const float* u          = (const float*)d_in[0];
    const float* norm_scale = (const float*)d_in[1];
    const float* norm_bias  = (const float*)d_in[2];
    const float* in_proj_w  = (const float*)d_in[3];
    const float* A_log      = (const float*)d_in[4];
    const float* dt_bias    = (const float*)d_in[5];
    const float* bcB_scale  = (const float*)d_in[6];
    const float* bcC_scale  = (const float*)d_in[7];
    const float* B_bias     = (const float*)d_in[8];
    const float* C_bias     = (const float*)d_in[9];
    const float* theta_w    = (const float*)d_in[10];
    const float* Dv         = (const float*)d_in[11];
    const float* out_proj_w = (const float*)d_in[12];
    float* out = (float*)d_out;

    float* p_xin  = sym_addr(g_xin);
    float* p_proj = sym_addr(g_proj);
    float* p_yz   = sym_addr(g_yz);

    // 1. layernorm + theta
    k_ln_theta<<<MROWS, 256>>>(u, norm_scale, norm_bias, theta_w);
    // 2. proj = x_in @ in_proj_w   (16384 x 1024 x 4256)
    k_sgemm<false><<<dim3((PROJ + 127) / 128, MROWS / 128), 256>>>(
        p_xin, in_proj_w, nullptr, p_proj, MROWS, PROJ, DMODEL);
    // 3. elementwise prep
    k_prep<<<MROWS, 256>>>(A_log, dt_bias, bcB_scale, bcC_scale, B_bias, C_bias);
    // 4. cumsum(phi)
    k_cs_chunk<<<BB * 64, 32>>>();
    k_cs_scan<<<1, 128>>>();
    k_cs_add<<<BB * 64, 256>>>();
    // 5. RoPE
    k_rope<<<MROWS / 8, 256>>>();
    // 6. SSD scan
    k_scan<<<256, 256>>>(Dv);
    // 7. gate
    k_mul<<<(MROWS * DINNER) / (256 * 4), 256>>>();
    // 8. out = yz @ out_proj_w + u   (16384 x 2048 x 1024)
    k_sgemm<true><<<dim3(DMODEL / 128, MROWS / 128), 256>>>(
        p_yz, out_proj_w, u, out, MROWS, DMODEL, DINNER);
}

// round 3
// speedup vs baseline: 1.7552x; 1.7552x over previous
#include <cuda_runtime.h>
#include <cuda_bf16.h>
#include <math.h>
#include <stdint.h>

// ---------------- problem constants ----------------
#define BB      4
#define LL      4096
#define DMODEL  1024
#define DINNER  2048
#define NHEADS  16
#define DSTATE  64
#define PROJ    4256
#define MROWS   (BB*LL)          // 16384
#define NPAD1   4352             // 34 * 128
#define K3_1    (3*DMODEL)       // 3072
#define K3_2    (3*DINNER)       // 6144

// ---------------- scratch (__device__ globals; no runtime alloc) -------------
__device__ __align__(16) float g_proj [(size_t)MROWS * PROJ];
__device__ __align__(16) float g_xs   [(size_t)MROWS * DINNER];
__device__ __align__(16) float g_yfull[(size_t)MROWS * DINNER];
__device__ __align__(16) float g_Bc   [(size_t)MROWS * DSTATE];
__device__ __align__(16) float g_Cc   [(size_t)MROWS * DSTATE];
__device__ __align__(16) float g_coef [(size_t)MROWS * NHEADS * 4];
__device__ __align__(16) float g_theta[(size_t)MROWS * 32];
__device__ __align__(16) float g_phi  [(size_t)MROWS * 32];
__device__ __align__(16) float g_csum [(size_t)BB * 64 * 32];
// K-tripled bf16 operands: A'' = [hi, lo, hi], B'' = [hi, hi, lo]
__device__ __align__(16) __nv_bfloat16 g_a3 [(size_t)MROWS * K3_1];
__device__ __align__(16) __nv_bfloat16 g_yz3[(size_t)MROWS * K3_2];
__device__ __align__(16) __nv_bfloat16 g_w31[(size_t)NPAD1 * K3_1];
__device__ __align__(16) __nv_bfloat16 g_w32[(size_t)DMODEL * K3_2];

// ---------------- PTX helpers --------------------------------------------------
__device__ __forceinline__ uint32_t s2u(const void* p)
{
    uint32_t r;
    asm("{ .reg .u64 t; cvta.to.shared.u64 t, %1; cvt.u32.u64 %0, t; }"
        : "=r"(r) : "l"(p));
    return r;
}
__device__ __forceinline__ void cp16(uint32_t d, const void* s)
{
    asm volatile("cp.async.cg.shared.global [%0], [%1], 16;" :: "r"(d), "l"(s));
}
#define CP_COMMIT() asm volatile("cp.async.commit_group;" ::: "memory")
#define CP_WAIT1()  asm volatile("cp.async.wait_group 1;"  ::: "memory")

__device__ __forceinline__ void ldm4(uint32_t* r, uint32_t a)
{
    asm volatile("ldmatrix.sync.aligned.m8n8.x4.shared.b16 {%0,%1,%2,%3}, [%4];"
        : "=r"(r[0]), "=r"(r[1]), "=r"(r[2]), "=r"(r[3]) : "r"(a));
}
__device__ __forceinline__ void mma16816(float* d, const uint32_t* a, const uint32_t* b)
{
    asm volatile("mma.sync.aligned.m16n8k16.row.col.f32.bf16.bf16.f32 "
        "{%0,%1,%2,%3}, {%4,%5,%6,%7}, {%8,%9}, {%0,%1,%2,%3};"
        : "+f"(d[0]), "+f"(d[1]), "+f"(d[2]), "+f"(d[3])
        : "r"(a[0]), "r"(a[1]), "r"(a[2]), "r"(a[3]), "r"(b[0]), "r"(b[1]));
}

// ---------------- layernorm + K3 hi/lo pack + theta -----------------------------
__global__ void __launch_bounds__(256) k_ln_theta(const float* __restrict__ u,
        const float* __restrict__ gscale, const float* __restrict__ gbias,
        const float* __restrict__ tw)
{
    __shared__ float su[1024];
    __shared__ float rsum[8], rsq[8];
    __shared__ float s_mu, s_rs;
    __shared__ float sth[8][32];
    int m = blockIdx.x, tid = threadIdx.x;
    const float* ur = u + (size_t)m * 1024 + tid * 4;
    float4 v = *(const float4*)ur;
    *(float4*)(su + tid * 4) = v;
    float s = v.x + v.y + v.z + v.w;
    float q = v.x*v.x + v.y*v.y + v.z*v.z + v.w*v.w;
    #pragma unroll
    for (int o = 16; o; o >>= 1) {
        s += __shfl_xor_sync(0xffffffffu, s, o);
        q += __shfl_xor_sync(0xffffffffu, q, o);
    }
    int lane = tid & 31, wid = tid >> 5;
    if (lane == 0) { rsum[wid] = s; rsq[wid] = q; }
    __syncthreads();
    if (tid == 0) {
        float S = 0.f, Q = 0.f;
        #pragma unroll
        for (int i = 0; i < 8; i++) { S += rsum[i]; Q += rsq[i]; }
        float mu  = S * (1.f / 1024.f);
        float var = Q * (1.f / 1024.f) - mu * mu;
        s_mu = mu;
        s_rs = rsqrtf(var + 1e-6f);
    }
    __syncthreads();
    float mu = s_mu, rs = s_rs;
    float4 sc = *(const float4*)(gscale + tid * 4);
    float4 bi = *(const float4*)(gbias  + tid * 4);
    float o0 = (v.x - mu) * rs * sc.x + bi.x;
    float o1 = (v.y - mu) * rs * sc.y + bi.y;
    float o2 = (v.z - mu) * rs * sc.z + bi.z;
    float o3 = (v.w - mu) * rs * sc.w + bi.w;
    __nv_bfloat16 h0 = __float2bfloat16(o0), h1 = __float2bfloat16(o1);
    __nv_bfloat16 h2 = __float2bfloat16(o2), h3 = __float2bfloat16(o3);
    __nv_bfloat162 hi01 = {h0, h1}, hi23 = {h2, h3};
    __nv_bfloat162 lo01 = {__float2bfloat16(o0 - __bfloat162float(h0)),
                           __float2bfloat16(o1 - __bfloat162float(h1))};
    __nv_bfloat162 lo23 = {__float2bfloat16(o2 - __bfloat162float(h2)),
                           __float2bfloat16(o3 - __bfloat162float(h3))};
    __nv_bfloat16* row = g_a3 + (size_t)m * K3_1;
    *(__nv_bfloat162*)(row + tid * 4)            = hi01;
    *(__nv_bfloat162*)(row + tid * 4 + 2)        = hi23;
    *(__nv_bfloat162*)(row + 1024 + tid * 4)     = lo01;
    *(__nv_bfloat162*)(row + 1024 + tid * 4 + 2) = lo23;
    *(__nv_bfloat162*)(row + 2048 + tid * 4)     = hi01;
    *(__nv_bfloat162*)(row + 2048 + tid * 4 + 2) = hi23;

    // theta = u_row @ theta_w (32 cols)
    int c = tid & 31, kc = tid >> 5;
    float acc = 0.f;
    const float* twp = tw + kc * 128 * 32 + c;
    const float* sup = su + kc * 128;
    #pragma unroll 8
    for (int kk = 0; kk < 128; ++kk) acc = fmaf(sup[kk], twp[kk * 32], acc);
    sth[kc][c] = acc;
    __syncthreads();
    if (tid < 32) {
        float t2 = 0.f;
        #pragma unroll
        for (int i = 0; i < 8; i++) t2 += sth[i][tid];
        g_theta[(size_t)m * 32 + tid] = t2;
    }
}

// ---------------- weight transpose + K3 split: T[n][3K] = [hi, hi, lo] ---------
__global__ void k_tsplit(const float* __restrict__ W, int K, int N,
                         __nv_bfloat16* __restrict__ T)
{
    __shared__ float t[32][33];
    int nb = blockIdx.x * 32, kb = blockIdx.y * 32;
    int x = threadIdx.x, y = threadIdx.y;   // 32 x 8
    #pragma unroll
    for (int i = 0; i < 32; i += 8) {
        int k = kb + y + i, n = nb + x;
        t[y + i][x] = (n < N) ? W[(size_t)k * N + n] : 0.f;
    }
    __syncthreads();
    #pragma unroll
    for (int i = 0; i < 32; i += 8) {
        int n = nb + y + i, k = kb + x;
        float v = t[x][y + i];
        __nv_bfloat16 h = __float2bfloat16(v);
        __nv_bfloat16 l = __float2bfloat16(v - __bfloat162float(h));
        __nv_bfloat16* row = T + (size_t)n * 3 * K;
        row[k]         = h;
        row[K + k]     = h;
        row[2 * K + k] = l;
    }
}

// ---------------- mma.sync bf16 GEMM --------------------------------------------
// C[M,N] = A[M,Kp] @ B[N,Kp]^T, fp32 acc. CTA 128x128, BK=64, 3-stage cp.async.
#define GSTAGE 32768
#define GSMEM  (3 * GSTAGE)

template<bool WITH_ADD>
__global__ void __launch_bounds__(256)
k_gemm_mma(const __nv_bfloat16* __restrict__ A, const __nv_bfloat16* __restrict__ B,
           const float* __restrict__ ADD, float* __restrict__ C, int N, int Kp)
{
    extern __shared__ char sm[];
    uint32_t smu = s2u(sm);
    int tid = threadIdx.x, wid = tid >> 5, lane = tid & 31;
    int n0 = blockIdx.x * 128, m0 = blockIdx.y * 128;
    int KT = Kp >> 6;

    // async copy of stage kt into slot
    auto issue = [&](int kt, int slot) {
        uint32_t st = smu + slot * GSTAGE;
        size_t k0 = (size_t)kt * 64;
        #pragma unroll
        for (int t = 0; t < 4; ++t) {
            int idx = tid + t * 256;
            int rw = idx >> 3, c = idx & 7;
            uint32_t sw = (uint32_t)(rw * 128) + (uint32_t)((c ^ (rw & 7)) << 4);
            cp16(st + sw, A + (size_t)(m0 + rw) * Kp + k0 + c * 8);
        }
        #pragma unroll
        for (int t = 0; t < 4; ++t) {
            int idx = tid + t * 256;
            int rw = idx >> 3, c = idx & 7;
            uint32_t sw = (uint32_t)(rw * 128) + (uint32_t)((c ^ (rw & 7)) << 4);
            cp16(st + 16384 + sw, B + (size_t)(n0 + rw) * Kp + k0 + c * 8);
        }
    };

    issue(0, 0); CP_COMMIT();
    issue(1, 1); CP_COMMIT();

    float d[2][8][4];
    #pragma unroll
    for (int i = 0; i < 2; i++)
        #pragma unroll
        for (int j = 0; j < 8; j++)
            #pragma unroll
            for (int e = 0; e < 4; e++) d[i][j][e] = 0.f;

    int mo = (wid >> 1) * 32, no = (wid & 1) * 64;

    for (int kt = 0; kt < KT; ++kt) {
        CP_WAIT1();
        __syncthreads();
        if (kt + 2 < KT) issue(kt + 2, (kt + 2) % 3);
        CP_COMMIT();

        uint32_t sA = smu + (kt % 3) * GSTAGE;
        uint32_t sB = sA + 16384;
        #pragma unroll
        for (int ks = 0; ks < 4; ++ks) {
            uint32_t a0[4], a1[4], bfr[4][4];
            {
                int r = mo + (lane & 15);
                int c = ks * 2 + (lane >> 4);
                ldm4(a0, sA + (uint32_t)(r * 128) + (uint32_t)((c ^ (r & 7)) << 4));
                r += 16;
                ldm4(a1, sA + (uint32_t)(r * 128) + (uint32_t)((c ^ (r & 7)) << 4));
            }
            #pragma unroll
            for (int nb = 0; nb < 4; ++nb) {
                int r = no + nb * 16 + (lane & 7) + (((lane >> 4) & 1) << 3);
                int c = ks * 2 + ((lane >> 3) & 1);
                ldm4(bfr[nb], sB + (uint32_t)(r * 128) + (uint32_t)((c ^ (r & 7)) << 4));
            }
            #pragma unroll
            for (int ni = 0; ni < 8; ++ni) {
                mma16816(d[0][ni], a0, &bfr[ni >> 1][(ni & 1) * 2]);
                mma16816(d[1][ni], a1, &bfr[ni >> 1][(ni & 1) * 2]);
            }
        }
    }

    // epilogue
    #pragma unroll
    for (int mi = 0; mi < 2; ++mi) {
        int r0 = m0 + mo + mi * 16 + (lane >> 2);
        #pragma unroll
        for (int ni = 0; ni < 8; ++ni) {
            int col = n0 + no + ni * 8 + (lane & 3) * 2;
            if (col < N) {
                float2 v0 = {d[mi][ni][0], d[mi][ni][1]};
                float2 v1 = {d[mi][ni][2], d[mi][ni][3]};
                if (WITH_ADD) {
                    float2 a0 = *(const float2*)(ADD + (size_t)r0 * N + col);
                    float2 a1 = *(const float2*)(ADD + (size_t)(r0 + 8) * N + col);
                    v0.x += a0.x; v0.y += a0.y;
                    v1.x += a1.x; v1.y += a1.y;
                }
                *(float2*)(C + (size_t)r0 * N + col)       = v0;
                *(float2*)(C + (size_t)(r0 + 8) * N + col) = v1;
            }
        }
    }
}

// ---------------- per-row prep ------------------------------------------------
__global__ void __launch_bounds__(256) k_prep(const float* __restrict__ A_log,
        const float* __restrict__ dt_bias,
        const float* __restrict__ bcB, const float* __restrict__ bcC,
        const float* __restrict__ Bbias, const float* __restrict__ Cbias)
{
    int m = blockIdx.x, tid = threadIdx.x;
    const float* row = g_proj + (size_t)m * PROJ;
    __shared__ float s_dts;

    #pragma unroll
    for (int it = 0; it < 2; ++it) {
        int j4 = tid + it * 256;
        float4 v = *(const float4*)(row + j4 * 4);
        float4 o;
        o.x = v.x / (1.f + expf(-v.x));
        o.y = v.y / (1.f + expf(-v.y));
        o.z = v.z / (1.f + expf(-v.z));
        o.w = v.w / (1.f + expf(-v.w));
        *(float4*)(g_xs + (size_t)m * DINNER + j4 * 4) = o;
    }

    int lane = tid & 31, wid = tid >> 5;
    if (wid == 0) {
        float b0 = row[4096 + lane], b1 = row[4128 + lane];
        float ss = b0 * b0 + b1 * b1;
        #pragma unroll
        for (int o = 16; o; o >>= 1) ss += __shfl_xor_sync(0xffffffffu, ss, o);
        float r = rsqrtf(ss * (1.f / 64.f) + 1e-6f);
        g_Bc[(size_t)m * 64 + lane]      = b0 * r * bcB[lane]      + Bbias[lane];
        g_Bc[(size_t)m * 64 + 32 + lane] = b1 * r * bcB[32 + lane] + Bbias[32 + lane];
    } else if (wid == 1) {
        float b0 = row[4160 + lane], b1 = row[4192 + lane];
        float ss = b0 * b0 + b1 * b1;
        #pragma unroll
        for (int o = 16; o; o >>= 1) ss += __shfl_xor_sync(0xffffffffu, ss, o);
        float r = rsqrtf(ss * (1.f / 64.f) + 1e-6f);
        g_Cc[(size_t)m * 64 + lane]      = b0 * r * bcC[lane]      + Cbias[lane];
        g_Cc[(size_t)m * 64 + 32 + lane] = b1 * r * bcC[32 + lane] + Cbias[32 + lane];
    } else if (wid == 2) {
        float dt = 0.f;
        if (lane < 16) {
            float x = row[4224 + lane] + dt_bias[lane];
            dt = (x > 20.f) ? x : log1pf(expf(x));
            float lamr = row[4240 + lane];
            float lam = 1.f / (1.f + expf(-lamr));
            float a = expf(-expf(A_log[lane]) * dt);
            size_t o = ((size_t)m * 16 + lane) * 4;
            g_coef[o]     = a;
            g_coef[o + 1] = dt * lam;
            g_coef[o + 2] = dt * (1.f - lam) * a;
            g_coef[o + 3] = 0.f;
        }
        float s = dt;
        #pragma unroll
        for (int o = 16; o; o >>= 1) s += __shfl_xor_sync(0xffffffffu, s, o);
        if (lane == 0) s_dts = s * (1.f / 16.f);
    }
    __syncthreads();
    if (tid < 32)
        g_phi[(size_t)m * 32 + tid] = s_dts * g_theta[(size_t)m * 32 + tid];
}

// ---------------- 3-phase cumsum ------------------------------------------------
__global__ void k_cs_chunk()
{
    int b = blockIdx.x >> 6, ch = blockIdx.x & 63;
    int c = threadIdx.x;
    size_t base = (((size_t)b * 4096) + (size_t)ch * 64) * 32 + c;
    float acc = 0.f;
    #pragma unroll 8
    for (int l = 0; l < 64; ++l) {
        acc += g_phi[base + (size_t)l * 32];
        g_phi[base + (size_t)l * 32] = acc;
    }
    g_csum[((size_t)(b * 64 + ch)) * 32 + c] = acc;
}
__global__ void k_cs_scan()
{
    int tid = threadIdx.x;
    int b = tid >> 5, c = tid & 31;
    float acc = 0.f;
    for (int ch = 0; ch < 64; ++ch) {
        size_t o = ((size_t)(b * 64 + ch)) * 32 + c;
        float t = g_csum[o];
        g_csum[o] = acc;
        acc += t;
    }
}
__global__ void k_cs_add()
{
    int b = blockIdx.x >> 6, ch = blockIdx.x & 63;
    __shared__ float off[32];
    if (threadIdx.x < 32)
        off[threadIdx.x] = g_csum[((size_t)(b * 64 + ch)) * 32 + threadIdx.x];
    __syncthreads();
    size_t base = (((size_t)b * 4096) + (size_t)ch * 64) * 32;
    for (int e = threadIdx.x; e < 2048; e += 256)
        g_phi[base + e] += off[e & 31];
}

// ---------------- RoPE ---------------------------------------------------------
__global__ void k_rope()
{
    int tid = threadIdx.x;
    int r = tid >> 5, lane = tid & 31;
    size_t m = (size_t)blockIdx.x * 8 + r;
    float ph = g_phi[m * 32 + lane];
    float cc = cosf(ph), ss = sinf(ph);
    size_t o = m * 64 + lane;
    float xr = g_Bc[o], xi = g_Bc[o + 32];
    g_Bc[o]      = xr * cc - xi * ss;
    g_Bc[o + 32] = xr * ss + xi * cc;
    xr = g_Cc[o]; xi = g_Cc[o + 32];
    g_Cc[o]      = xr * cc - xi * ss;
    g_Cc[o + 32] = xr * ss + xi * cc;
}

// ---------------- SSD trapezoidal scan ------------------------------------------
__global__ void __launch_bounds__(256) k_scan(const float* __restrict__ Dv)
{
    int bx = blockIdx.x;
    int pg = bx & 3, h = (bx >> 2) & 15, b = bx >> 6;
    int tid = threadIdx.x;
    int nsub = tid & 7, pl = tid >> 3;
    int p = pg * 32 + pl;
    size_t mb = (size_t)b * 4096;
    const float* Bp = g_Bc + mb * 64 + nsub * 8;
    const float* Cp = g_Cc + mb * 64 + nsub * 8;
    const float* Kp = g_coef + (mb * 16 + h) * 4;
    const float* Xp = g_xs + mb * 2048 + h * 128 + p;
    float*       Yp = g_yfull + mb * 2048 + h * 128 + p;
    float Dh = Dv[h];

    float hs[8], Bprev[8];
    #pragma unroll
    for (int i = 0; i < 8; i++) { hs[i] = 0.f; Bprev[i] = 0.f; }
    float xprev = 0.f;

    float4 b0 = *(const float4*)Bp;
    float4 b1 = *(const float4*)(Bp + 4);
    float4 c0 = *(const float4*)Cp;
    float4 c1 = *(const float4*)(Cp + 4);
    float4 cf = *(const float4*)Kp;
    float  xc = *Xp;

    for (int t = 0; t < 4096; ++t) {
        float4 nb0 = b0, nb1 = b1, nc0 = c0, nc1 = c1, ncf = cf;
        float nx = xc;
        if (t < 4095) {
            Bp += 64; Cp += 64; Kp += 64; Xp += 2048;
            nb0 = *(const float4*)Bp; nb1 = *(const float4*)(Bp + 4);
            nc0 = *(const float4*)Cp; nc1 = *(const float4*)(Cp + 4);
            ncf = *(const float4*)Kp; nx = *Xp;
        }
        float ca  = cf.x;
        float c1x = cf.y * xc;
        float c2x = cf.z * xprev;
        float Bn[8] = {b0.x, b0.y, b0.z, b0.w, b1.x, b1.y, b1.z, b1.w};
        float Cn[8] = {c0.x, c0.y, c0.z, c0.w, c1.x, c1.y, c1.z, c1.w};
        float acc = 0.f;
        #pragma unroll
        for (int i = 0; i < 8; i++) {
            float bx_ = fmaf(c1x, Bn[i], c2x * Bprev[i]);
            hs[i] = fmaf(ca, hs[i], bx_);
            acc = fmaf(hs[i], Cn[i], acc);
            Bprev[i] = Bn[i];
        }
        xprev = xc;
        acc += __shfl_xor_sync(0xffffffffu, acc, 1);
        acc += __shfl_xor_sync(0xffffffffu, acc, 2);
        acc += __shfl_xor_sync(0xffffffffu, acc, 4);
        if (nsub == 0) *Yp = fmaf(Dh, xc, acc);
        Yp += 2048;
        b0 = nb0; b1 = nb1; c0 = nc0; c1 = nc1; cf = ncf; xc = nx;
    }
}

// ---------------- yz = y_full * silu(z) -> K3 pack -------------------------------
__global__ void k_mul()
{
    size_t f4 = (size_t)blockIdx.x * 256 + threadIdx.x;
    size_t flat = f4 * 4;
    size_t m = flat >> 11;
    int j = (int)(flat & 2047);
    float4 y = *(const float4*)(g_yfull + flat);
    float4 z = *(const float4*)(g_proj + m * PROJ + 2048 + j);
    float o0 = y.x * (z.x / (1.f + expf(-z.x)));
    float o1 = y.y * (z.y / (1.f + expf(-z.y)));
    float o2 = y.z * (z.z / (1.f + expf(-z.z)));
    float o3 = y.w * (z.w / (1.f + expf(-z.w)));
    __nv_bfloat16 h0 = __float2bfloat16(o0), h1 = __float2bfloat16(o1);
    __nv_bfloat16 h2 = __float2bfloat16(o2), h3 = __float2bfloat16(o3);
    __nv_bfloat162 hi01 = {h0, h1}, hi23 = {h2, h3};
    __nv_bfloat162 lo01 = {__float2bfloat16(o0 - __bfloat162float(h0)),
                           __float2bfloat16(o1 - __bfloat162float(h1))};
    __nv_bfloat162 lo23 = {__float2bfloat16(o2 - __bfloat162float(h2)),
                           __float2bfloat16(o3 - __bfloat162float(h3))};
    __nv_bfloat16* row = g_yz3 + m * K3_2;
    *(__nv_bfloat162*)(row + j)            = hi01;
    *(__nv_bfloat162*)(row + j + 2)        = hi23;
    *(__nv_bfloat162*)(row + 2048 + j)     = lo01;
    *(__nv_bfloat162*)(row + 2048 + j + 2) = lo23;
    *(__nv_bfloat162*)(row + 4096 + j)     = hi01;
    *(__nv_bfloat162*)(row + 4096 + j + 2) = hi23;
}

// ---------------- host launcher --------------------------------------------------
template<typename T>
static T* sym_addr(const void* s)
{
    void* p = nullptr;
    cudaGetSymbolAddress(&p, s);
    return (T*)p;
}

extern "C" void kernel_launch(void* const* d_in, const int* in_sizes, int n_in,
                              void* d_out, int out_size)
{
    const float* u          = (const float*)d_in[0];
    const float* norm_scale = (const float*)d_in[1];
    const float* norm_bias  = (const float*)d_in[2];
    const float* in_proj_w  = (const float*)d_in[3];
    const float* A_log      = (const float*)d_in[4];
    const float* dt_bias    = (const float*)d_in[5];
    const float* bcB_scale  = (const float*)d_in[6];
    const float* bcC_scale  = (const float*)d_in[7];
    const float* B_bias     = (const float*)d_in[8];
    const float* C_bias     = (const float*)d_in[9];
    const float* theta_w    = (const float*)d_in[10];
    const float* Dv         = (const float*)d_in[11];
    const float* out_proj_w = (const float*)d_in[12];
    float* out = (float*)d_out;

    float* p_proj = sym_addr<float>(g_proj);
    __nv_bfloat16* p_a3  = sym_addr<__nv_bfloat16>(g_a3);
    __nv_bfloat16* p_yz3 = sym_addr<__nv_bfloat16>(g_yz3);
    __nv_bfloat16* p_w31 = sym_addr<__nv_bfloat16>(g_w31);
    __nv_bfloat16* p_w32 = sym_addr<__nv_bfloat16>(g_w32);

    static bool attr_done = false;
    if (!attr_done) {
        cudaFuncSetAttribute(k_gemm_mma<false>,
            cudaFuncAttributeMaxDynamicSharedMemorySize, GSMEM);
        cudaFuncSetAttribute(k_gemm_mma<true>,
            cudaFuncAttributeMaxDynamicSharedMemorySize, GSMEM);
        attr_done = true;
    }

    // 1. layernorm + hi/lo pack + theta
    k_ln_theta<<<MROWS, 256>>>(u, norm_scale, norm_bias, theta_w);
    // 2. weight transpose + hi/lo pack
    k_tsplit<<<dim3(NPAD1 / 32, DMODEL / 32), dim3(32, 8)>>>(
        in_proj_w, DMODEL, PROJ, p_w31);
    k_tsplit<<<dim3(DMODEL / 32, DINNER / 32), dim3(32, 8)>>>(
        out_proj_w, DINNER, DMODEL, p_w32);
    // 3. proj = x_in @ in_proj_w  (mma.sync bf16, K tripled)
    k_gemm_mma<false><<<dim3(NPAD1 / 128, MROWS / 128), 256, GSMEM>>>(
        p_a3, p_w31, nullptr, p_proj, PROJ, K3_1);
    // 4. elementwise prep
    k_prep<<<MROWS, 256>>>(A_log, dt_bias, bcB_scale, bcC_scale, B_bias, C_bias);
    // 5. cumsum(phi)
    k_cs_chunk<<<BB * 64, 32>>>();
    k_cs_scan<<<1, 128>>>();
    k_cs_add<<<BB * 64, 256>>>();
    // 6. RoPE
    k_rope<<<MROWS / 8, 256>>>();
    // 7. SSD scan
    k_scan<<<256, 256>>>(Dv);
    // 8. gate + hi/lo pack
    k_mul<<<(MROWS * DINNER) / (256 * 4), 256>>>();
    // 9. out = yz @ out_proj_w + u  (mma.sync bf16, K tripled)
    k_gemm_mma<true><<<dim3(DMODEL / 128, MROWS / 128), 256, GSMEM>>>(
        p_yz3, p_w32, u, out, DMODEL, K3_2);
}

// round 4
// speedup vs baseline: 2.4805x; 1.4132x over previous
#include <cuda_runtime.h>
#include <cuda_bf16.h>
#include <math.h>
#include <stdint.h>

// ---------------- problem constants ----------------
#define BB      4
#define LL      4096
#define DMODEL  1024
#define DINNER  2048
#define NHEADS  16
#define DSTATE  64
#define PROJ    4256
#define MROWS   (BB*LL)          // 16384
#define NPAD1   4352             // 34 * 128
#define K3_1    (3*DMODEL)       // 3072
#define K3_2    (3*DINNER)       // 6144

// ---------------- scratch (__device__ globals; no runtime alloc) -------------
__device__ __align__(16) float g_xs   [(size_t)MROWS * DINNER];   // silu(x)
__device__ __align__(16) float g_sz   [(size_t)MROWS * DINNER];   // silu(z)
__device__ __align__(16) float g_tail [(size_t)MROWS * 160];      // B,C,dt,lam raw
__device__ __align__(16) float g_yfull[(size_t)MROWS * DINNER];
__device__ __align__(16) float g_Bc   [(size_t)MROWS * DSTATE];
__device__ __align__(16) float g_Cc   [(size_t)MROWS * DSTATE];
__device__ __align__(16) float g_coef [(size_t)MROWS * NHEADS * 4];
__device__ __align__(16) float g_theta[(size_t)MROWS * 32];
__device__ __align__(16) float g_phi  [(size_t)MROWS * 32];
__device__ __align__(16) float g_csum [(size_t)BB * 64 * 32];
// K-tripled bf16 operands: A'' = [hi, lo, hi], B'' = [hi, hi, lo]
__device__ __align__(16) __nv_bfloat16 g_a3 [(size_t)MROWS * K3_1];
__device__ __align__(16) __nv_bfloat16 g_yz3[(size_t)MROWS * K3_2];
__device__ __align__(16) __nv_bfloat16 g_w31[(size_t)NPAD1 * K3_1];
__device__ __align__(16) __nv_bfloat16 g_w32[(size_t)DMODEL * K3_2];

// ---------------- PTX helpers --------------------------------------------------
__device__ __forceinline__ uint32_t s2u(const void* p)
{
    uint32_t r;
    asm("{ .reg .u64 t; cvta.to.shared.u64 t, %1; cvt.u32.u64 %0, t; }"
        : "=r"(r) : "l"(p));
    return r;
}
__device__ __forceinline__ void cp16(uint32_t d, const void* s)
{
    asm volatile("cp.async.cg.shared.global [%0], [%1], 16;" :: "r"(d), "l"(s));
}
#define CP_COMMIT() asm volatile("cp.async.commit_group;" ::: "memory")
#define CP_WAIT1()  asm volatile("cp.async.wait_group 1;"  ::: "memory")

__device__ __forceinline__ void ldm4(uint32_t* r, uint32_t a)
{
    asm volatile("ldmatrix.sync.aligned.m8n8.x4.shared.b16 {%0,%1,%2,%3}, [%4];"
        : "=r"(r[0]), "=r"(r[1]), "=r"(r[2]), "=r"(r[3]) : "r"(a));
}
__device__ __forceinline__ void mma16816(float* d, const uint32_t* a, const uint32_t* b)
{
    asm volatile("mma.sync.aligned.m16n8k16.row.col.f32.bf16.bf16.f32 "
        "{%0,%1,%2,%3}, {%4,%5,%6,%7}, {%8,%9}, {%0,%1,%2,%3};"
        : "+f"(d[0]), "+f"(d[1]), "+f"(d[2]), "+f"(d[3])
        : "r"(a[0]), "r"(a[1]), "r"(a[2]), "r"(a[3]), "r"(b[0]), "r"(b[1]));
}
__device__ __forceinline__ float silu1(float v)
{
    return v / (1.f + expf(-v));
}

// ---------------- layernorm + K3 hi/lo pack + theta -----------------------------
__global__ void __launch_bounds__(256) k_ln_theta(const float* __restrict__ u,
        const float* __restrict__ gscale, const float* __restrict__ gbias,
        const float* __restrict__ tw)
{
    __shared__ float su[1024];
    __shared__ float rsum[8], rsq[8];
    __shared__ float s_mu, s_rs;
    __shared__ float sth[8][32];
    int m = blockIdx.x, tid = threadIdx.x;
    const float* ur = u + (size_t)m * 1024 + tid * 4;
    float4 v = *(const float4*)ur;
    *(float4*)(su + tid * 4) = v;
    float s = v.x + v.y + v.z + v.w;
    float q = v.x*v.x + v.y*v.y + v.z*v.z + v.w*v.w;
    #pragma unroll
    for (int o = 16; o; o >>= 1) {
        s += __shfl_xor_sync(0xffffffffu, s, o);
        q += __shfl_xor_sync(0xffffffffu, q, o);
    }
    int lane = tid & 31, wid = tid >> 5;
    if (lane == 0) { rsum[wid] = s; rsq[wid] = q; }
    __syncthreads();
    if (tid == 0) {
        float S = 0.f, Q = 0.f;
        #pragma unroll
        for (int i = 0; i < 8; i++) { S += rsum[i]; Q += rsq[i]; }
        float mu  = S * (1.f / 1024.f);
        float var = Q * (1.f / 1024.f) - mu * mu;
        s_mu = mu;
        s_rs = rsqrtf(var + 1e-6f);
    }
    __syncthreads();
    float mu = s_mu, rs = s_rs;
    float4 sc = *(const float4*)(gscale + tid * 4);
    float4 bi = *(const float4*)(gbias  + tid * 4);
    float o0 = (v.x - mu) * rs * sc.x + bi.x;
    float o1 = (v.y - mu) * rs * sc.y + bi.y;
    float o2 = (v.z - mu) * rs * sc.z + bi.z;
    float o3 = (v.w - mu) * rs * sc.w + bi.w;
    __nv_bfloat16 h0 = __float2bfloat16(o0), h1 = __float2bfloat16(o1);
    __nv_bfloat16 h2 = __float2bfloat16(o2), h3 = __float2bfloat16(o3);
    __nv_bfloat162 hi01 = {h0, h1}, hi23 = {h2, h3};
    __nv_bfloat162 lo01 = {__float2bfloat16(o0 - __bfloat162float(h0)),
                           __float2bfloat16(o1 - __bfloat162float(h1))};
    __nv_bfloat162 lo23 = {__float2bfloat16(o2 - __bfloat162float(h2)),
                           __float2bfloat16(o3 - __bfloat162float(h3))};
    __nv_bfloat16* row = g_a3 + (size_t)m * K3_1;
    *(__nv_bfloat162*)(row + tid * 4)            = hi01;
    *(__nv_bfloat162*)(row + tid * 4 + 2)        = hi23;
    *(__nv_bfloat162*)(row + 1024 + tid * 4)     = lo01;
    *(__nv_bfloat162*)(row + 1024 + tid * 4 + 2) = lo23;
    *(__nv_bfloat162*)(row + 2048 + tid * 4)     = hi01;
    *(__nv_bfloat162*)(row + 2048 + tid * 4 + 2) = hi23;

    // theta = u_row @ theta_w (32 cols)
    int c = tid & 31, kc = tid >> 5;
    float acc = 0.f;
    const float* twp = tw + kc * 128 * 32 + c;
    const float* sup = su + kc * 128;
    #pragma unroll 8
    for (int kk = 0; kk < 128; ++kk) acc = fmaf(sup[kk], twp[kk * 32], acc);
    sth[kc][c] = acc;
    __syncthreads();
    if (tid < 32) {
        float t2 = 0.f;
        #pragma unroll
        for (int i = 0; i < 8; i++) t2 += sth[i][tid];
        g_theta[(size_t)m * 32 + tid] = t2;
    }
}

// ---------------- weight transpose + K3 split: T[n][3K] = [hi, hi, lo] ---------
__global__ void k_tsplit(const float* __restrict__ W, int K, int N,
                         __nv_bfloat16* __restrict__ T)
{
    __shared__ float t[32][33];
    int nb = blockIdx.x * 32, kb = blockIdx.y * 32;
    int x = threadIdx.x, y = threadIdx.y;   // 32 x 8
    #pragma unroll
    for (int i = 0; i < 32; i += 8) {
        int k = kb + y + i, n = nb + x;
        t[y + i][x] = (n < N) ? W[(size_t)k * N + n] : 0.f;
    }
    __syncthreads();
    #pragma unroll
    for (int i = 0; i < 32; i += 8) {
        int n = nb + y + i, k = kb + x;
        float v = t[x][y + i];
        __nv_bfloat16 h = __float2bfloat16(v);
        __nv_bfloat16 l = __float2bfloat16(v - __bfloat162float(h));
        __nv_bfloat16* row = T + (size_t)n * 3 * K;
        row[k]         = h;
        row[K + k]     = h;
        row[2 * K + k] = l;
    }
}

// ---------------- mma.sync bf16 GEMM --------------------------------------------
// C[M,N] = A[M,Kp] @ B[N,Kp]^T, fp32 acc. CTA 128x128, BK=64, 3-stage cp.async.
// MODE 0: fused proj epilogue (silu(x)->g_xs, silu(z)->g_sz, tail->g_tail)
// MODE 1: C = result + ADD (residual)
#define GSTAGE 32768
#define GSMEM  (3 * GSTAGE)

template<int MODE>
__global__ void __launch_bounds__(256)
k_gemm_mma(const __nv_bfloat16* __restrict__ A, const __nv_bfloat16* __restrict__ B,
           const float* __restrict__ ADD, float* __restrict__ C, int N, int Kp)
{
    extern __shared__ char sm[];
    uint32_t smu = s2u(sm);
    int tid = threadIdx.x, wid = tid >> 5, lane = tid & 31;
    int n0 = blockIdx.x * 128, m0 = blockIdx.y * 128;
    int KT = Kp >> 6;

    auto issue = [&](int kt, int slot) {
        uint32_t st = smu + slot * GSTAGE;
        size_t k0 = (size_t)kt * 64;
        #pragma unroll
        for (int t = 0; t < 4; ++t) {
            int idx = tid + t * 256;
            int rw = idx >> 3, c = idx & 7;
            uint32_t sw = (uint32_t)(rw * 128) + (uint32_t)((c ^ (rw & 7)) << 4);
            cp16(st + sw, A + (size_t)(m0 + rw) * Kp + k0 + c * 8);
        }
        #pragma unroll
        for (int t = 0; t < 4; ++t) {
            int idx = tid + t * 256;
            int rw = idx >> 3, c = idx & 7;
            uint32_t sw = (uint32_t)(rw * 128) + (uint32_t)((c ^ (rw & 7)) << 4);
            cp16(st + 16384 + sw, B + (size_t)(n0 + rw) * Kp + k0 + c * 8);
        }
    };

    issue(0, 0); CP_COMMIT();
    issue(1, 1); CP_COMMIT();

    float d[2][8][4];
    #pragma unroll
    for (int i = 0; i < 2; i++)
        #pragma unroll
        for (int j = 0; j < 8; j++)
            #pragma unroll
            for (int e = 0; e < 4; e++) d[i][j][e] = 0.f;

    int mo = (wid >> 1) * 32, no = (wid & 1) * 64;

    for (int kt = 0; kt < KT; ++kt) {
        CP_WAIT1();
        __syncthreads();
        if (kt + 2 < KT) issue(kt + 2, (kt + 2) % 3);
        CP_COMMIT();

        uint32_t sA = smu + (kt % 3) * GSTAGE;
        uint32_t sB = sA + 16384;
        #pragma unroll
        for (int ks = 0; ks < 4; ++ks) {
            uint32_t a0[4], a1[4], bfr[4][4];
            {
                int r = mo + (lane & 15);
                int c = ks * 2 + (lane >> 4);
                ldm4(a0, sA + (uint32_t)(r * 128) + (uint32_t)((c ^ (r & 7)) << 4));
                r += 16;
                ldm4(a1, sA + (uint32_t)(r * 128) + (uint32_t)((c ^ (r & 7)) << 4));
            }
            #pragma unroll
            for (int nb = 0; nb < 4; ++nb) {
                int r = no + nb * 16 + (lane & 7) + (((lane >> 4) & 1) << 3);
                int c = ks * 2 + ((lane >> 3) & 1);
                ldm4(bfr[nb], sB + (uint32_t)(r * 128) + (uint32_t)((c ^ (r & 7)) << 4));
            }
            #pragma unroll
            for (int ni = 0; ni < 8; ++ni) {
                mma16816(d[0][ni], a0, &bfr[ni >> 1][(ni & 1) * 2]);
                mma16816(d[1][ni], a1, &bfr[ni >> 1][(ni & 1) * 2]);
            }
        }
    }

    // epilogue
    #pragma unroll
    for (int mi = 0; mi < 2; ++mi) {
        int r0 = m0 + mo + mi * 16 + (lane >> 2);
        #pragma unroll
        for (int ni = 0; ni < 8; ++ni) {
            int col = n0 + no + ni * 8 + (lane & 3) * 2;
            #pragma unroll
            for (int half = 0; half < 2; ++half) {
                int row = r0 + half * 8;
                float2 v = {d[mi][ni][half * 2], d[mi][ni][half * 2 + 1]};
                if (MODE == 0) {
                    if (col < 2048) {
                        float2 o = {silu1(v.x), silu1(v.y)};
                        *(float2*)(g_xs + (size_t)row * 2048 + col) = o;
                    } else if (col < 4096) {
                        float2 o = {silu1(v.x), silu1(v.y)};
                        *(float2*)(g_sz + (size_t)row * 2048 + col - 2048) = o;
                    } else if (col < 4256) {
                        *(float2*)(g_tail + (size_t)row * 160 + col - 4096) = v;
                    }
                } else {
                    if (col < N) {
                        float2 a2 = *(const float2*)(ADD + (size_t)row * N + col);
                        v.x += a2.x; v.y += a2.y;
                        *(float2*)(C + (size_t)row * N + col) = v;
                    }
                }
            }
        }
    }
}

// ---------------- per-row prep (tail only): rmsnorm B/C, dt/lam coefs, dphi ----
__global__ void __launch_bounds__(96) k_prep(const float* __restrict__ A_log,
        const float* __restrict__ dt_bias,
        const float* __restrict__ bcB, const float* __restrict__ bcC,
        const float* __restrict__ Bbias, const float* __restrict__ Cbias)
{
    int m = blockIdx.x, tid = threadIdx.x;
    const float* tail = g_tail + (size_t)m * 160;
    __shared__ float s_dts;

    int lane = tid & 31, wid = tid >> 5;
    if (wid == 0) {
        float b0 = tail[lane], b1 = tail[32 + lane];
        float ss = b0 * b0 + b1 * b1;
        #pragma unroll
        for (int o = 16; o; o >>= 1) ss += __shfl_xor_sync(0xffffffffu, ss, o);
        float r = rsqrtf(ss * (1.f / 64.f) + 1e-6f);
        g_Bc[(size_t)m * 64 + lane]      = b0 * r * bcB[lane]      + Bbias[lane];
        g_Bc[(size_t)m * 64 + 32 + lane] = b1 * r * bcB[32 + lane] + Bbias[32 + lane];
    } else if (wid == 1) {
        float b0 = tail[64 + lane], b1 = tail[96 + lane];
        float ss = b0 * b0 + b1 * b1;
        #pragma unroll
        for (int o = 16; o; o >>= 1) ss += __shfl_xor_sync(0xffffffffu, ss, o);
        float r = rsqrtf(ss * (1.f / 64.f) + 1e-6f);
        g_Cc[(size_t)m * 64 + lane]      = b0 * r * bcC[lane]      + Cbias[lane];
        g_Cc[(size_t)m * 64 + 32 + lane] = b1 * r * bcC[32 + lane] + Cbias[32 + lane];
    } else {
        float dt = 0.f;
        if (lane < 16) {
            float x = tail[128 + lane] + dt_bias[lane];
            dt = (x > 20.f) ? x : log1pf(expf(x));
            float lamr = tail[144 + lane];
            float lam = 1.f / (1.f + expf(-lamr));
            float a = expf(-expf(A_log[lane]) * dt);
            size_t o = ((size_t)m * 16 + lane) * 4;
            g_coef[o]     = a;
            g_coef[o + 1] = dt * lam;
            g_coef[o + 2] = dt * (1.f - lam) * a;
            g_coef[o + 3] = 0.f;
        }
        float s = dt;
        #pragma unroll
        for (int o = 16; o; o >>= 1) s += __shfl_xor_sync(0xffffffffu, s, o);
        if (lane == 0) s_dts = s * (1.f / 16.f);
    }
    __syncthreads();
    if (tid < 32)
        g_phi[(size_t)m * 32 + tid] = s_dts * g_theta[(size_t)m * 32 + tid];
}

// ---------------- 3-phase cumsum ------------------------------------------------
__global__ void k_cs_chunk()
{
    int b = blockIdx.x >> 6, ch = blockIdx.x & 63;
    int c = threadIdx.x;
    size_t base = (((size_t)b * 4096) + (size_t)ch * 64) * 32 + c;
    float acc = 0.f;
    #pragma unroll 8
    for (int l = 0; l < 64; ++l) {
        acc += g_phi[base + (size_t)l * 32];
        g_phi[base + (size_t)l * 32] = acc;
    }
    g_csum[((size_t)(b * 64 + ch)) * 32 + c] = acc;
}
__global__ void k_cs_scan()
{
    int tid = threadIdx.x;
    int b = tid >> 5, c = tid & 31;
    float acc = 0.f;
    for (int ch = 0; ch < 64; ++ch) {
        size_t o = ((size_t)(b * 64 + ch)) * 32 + c;
        float t = g_csum[o];
        g_csum[o] = acc;
        acc += t;
    }
}
__global__ void k_cs_add()
{
    int b = blockIdx.x >> 6, ch = blockIdx.x & 63;
    __shared__ float off[32];
    if (threadIdx.x < 32)
        off[threadIdx.x] = g_csum[((size_t)(b * 64 + ch)) * 32 + threadIdx.x];
    __syncthreads();
    size_t base = (((size_t)b * 4096) + (size_t)ch * 64) * 32;
    for (int e = threadIdx.x; e < 2048; e += 256)
        g_phi[base + e] += off[e & 31];
}

// ---------------- RoPE ---------------------------------------------------------
__global__ void k_rope()
{
    int tid = threadIdx.x;
    int r = tid >> 5, lane = tid & 31;
    size_t m = (size_t)blockIdx.x * 8 + r;
    float ph = g_phi[m * 32 + lane];
    float cc = cosf(ph), ss = sinf(ph);
    size_t o = m * 64 + lane;
    float xr = g_Bc[o], xi = g_Bc[o + 32];
    g_Bc[o]      = xr * cc - xi * ss;
    g_Bc[o + 32] = xr * ss + xi * cc;
    xr = g_Cc[o]; xi = g_Cc[o + 32];
    g_Cc[o]      = xr * cc - xi * ss;
    g_Cc[o + 32] = xr * ss + xi * cc;
}

// ---------------- SSD trapezoidal scan (cp.async smem pipeline) -----------------
// grid 256 = (b:4, h:16, pg:4); 256 threads: thread = (pl = tid>>3, nsub = tid&7)
#define SCHUNK 32
struct __align__(16) ScanStage {
    float B[SCHUNK][64];
    float C[SCHUNK][64];
    float x[SCHUNK][32];
    float cf[SCHUNK][4];
};

__global__ void __launch_bounds__(256) k_scan(const float* __restrict__ Dv)
{
    __shared__ ScanStage st[2];
    int bx = blockIdx.x;
    int pg = bx & 3, h = (bx >> 2) & 15, b = bx >> 6;
    int tid = threadIdx.x;
    int nsub = tid & 7, pl = tid >> 3;
    size_t mb = (size_t)b * 4096;
    const float* Bg = g_Bc + mb * 64;
    const float* Cg = g_Cc + mb * 64;
    const float* Xg = g_xs + mb * 2048 + h * 128 + pg * 32;
    const float* Kg = g_coef + (mb * 16 + h) * 4;
    float* Yp = g_yfull + mb * 2048 + h * 128 + pg * 32 + pl;
    float Dh = Dv[h];

    auto load_chunk = [&](int c, int slot) {
        int t0 = c * SCHUNK;
        #pragma unroll
        for (int i = 0; i < 2; ++i) {
            int idx = tid + i * 256;
            int t = idx >> 4, seg = idx & 15;
            cp16(s2u(&st[slot].B[t][seg * 4]), Bg + (size_t)(t0 + t) * 64 + seg * 4);
        }
        #pragma unroll
        for (int i = 0; i < 2; ++i) {
            int idx = tid + i * 256;
            int t = idx >> 4, seg = idx & 15;
            cp16(s2u(&st[slot].C[t][seg * 4]), Cg + (size_t)(t0 + t) * 64 + seg * 4);
        }
        {
            int t = tid >> 3, seg = tid & 7;
            cp16(s2u(&st[slot].x[t][seg * 4]), Xg + (size_t)(t0 + t) * 2048 + seg * 4);
        }
        if (tid < SCHUNK)
            cp16(s2u(&st[slot].cf[tid]), Kg + (size_t)(t0 + tid) * 64);
    };

    float hs[8], Bprev[8];
    #pragma unroll
    for (int i = 0; i < 8; i++) { hs[i] = 0.f; Bprev[i] = 0.f; }
    float xprev = 0.f;

    load_chunk(0, 0); CP_COMMIT();
    load_chunk(1, 1); CP_COMMIT();

    const int NCHUNK = LL / SCHUNK;   // 128
    for (int c = 0; c < NCHUNK; ++c) {
        int slot = c & 1;
        CP_WAIT1();
        __syncthreads();
        #pragma unroll 4
        for (int t = 0; t < SCHUNK; ++t) {
            float4 b0 = *(const float4*)&st[slot].B[t][nsub * 8];
            float4 b1 = *(const float4*)&st[slot].B[t][nsub * 8 + 4];
            float4 c0 = *(const float4*)&st[slot].C[t][nsub * 8];
            float4 c1 = *(const float4*)&st[slot].C[t][nsub * 8 + 4];
            float4 cf = *(const float4*)&st[slot].cf[t];
            float xc = st[slot].x[t][pl];
            float ca  = cf.x;
            float c1x = cf.y * xc;
            float c2x = cf.z * xprev;
            float Bn[8] = {b0.x, b0.y, b0.z, b0.w, b1.x, b1.y, b1.z, b1.w};
            float Cn[8] = {c0.x, c0.y, c0.z, c0.w, c1.x, c1.y, c1.z, c1.w};
            float acc = 0.f;
            #pragma unroll
            for (int i = 0; i < 8; i++) {
                float bx_ = fmaf(c1x, Bn[i], c2x * Bprev[i]);
                hs[i] = fmaf(ca, hs[i], bx_);
                acc = fmaf(hs[i], Cn[i], acc);
                Bprev[i] = Bn[i];
            }
            xprev = xc;
            acc += __shfl_xor_sync(0xffffffffu, acc, 1);
            acc += __shfl_xor_sync(0xffffffffu, acc, 2);
            acc += __shfl_xor_sync(0xffffffffu, acc, 4);
            if (nsub == 0)
                Yp[(size_t)(c * SCHUNK + t) * 2048] = fmaf(Dh, xc, acc);
        }
        __syncthreads();
        if (c + 2 < NCHUNK) load_chunk(c + 2, slot);
        CP_COMMIT();
    }
}

// ---------------- yz = y_full * silu(z) -> K3 pack -------------------------------
__global__ void k_mul()
{
    size_t f4 = (size_t)blockIdx.x * 256 + threadIdx.x;
    size_t flat = f4 * 4;
    size_t m = flat >> 11;
    int j = (int)(flat & 2047);
    float4 y = *(const float4*)(g_yfull + flat);
    float4 z = *(const float4*)(g_sz + flat);
    float o0 = y.x * z.x;
    float o1 = y.y * z.y;
    float o2 = y.z * z.z;
    float o3 = y.w * z.w;
    __nv_bfloat16 h0 = __float2bfloat16(o0), h1 = __float2bfloat16(o1);
    __nv_bfloat16 h2 = __float2bfloat16(o2), h3 = __float2bfloat16(o3);
    __nv_bfloat162 hi01 = {h0, h1}, hi23 = {h2, h3};
    __nv_bfloat162 lo01 = {__float2bfloat16(o0 - __bfloat162float(h0)),
                           __float2bfloat16(o1 - __bfloat162float(h1))};
    __nv_bfloat162 lo23 = {__float2bfloat16(o2 - __bfloat162float(h2)),
                           __float2bfloat16(o3 - __bfloat162float(h3))};
    __nv_bfloat16* row = g_yz3 + m * K3_2;
    *(__nv_bfloat162*)(row + j)            = hi01;
    *(__nv_bfloat162*)(row + j + 2)        = hi23;
    *(__nv_bfloat162*)(row + 2048 + j)     = lo01;
    *(__nv_bfloat162*)(row + 2048 + j + 2) = lo23;
    *(__nv_bfloat162*)(row + 4096 + j)     = hi01;
    *(__nv_bfloat162*)(row + 4096 + j + 2) = hi23;
}

// ---------------- host launcher --------------------------------------------------
template<typename T>
static T* sym_addr(const void* s)
{
    void* p = nullptr;
    cudaGetSymbolAddress(&p, s);
    return (T*)p;
}

extern "C" void kernel_launch(void* const* d_in, const int* in_sizes, int n_in,
                              void* d_out, int out_size)
{
    const float* u          = (const float*)d_in[0];
    const float* norm_scale = (const float*)d_in[1];
    const float* norm_bias  = (const float*)d_in[2];
    const float* in_proj_w  = (const float*)d_in[3];
    const float* A_log      = (const float*)d_in[4];
    const float* dt_bias    = (const float*)d_in[5];
    const float* bcB_scale  = (const float*)d_in[6];
    const float* bcC_scale  = (const float*)d_in[7];
    const float* B_bias     = (const float*)d_in[8];
    const float* C_bias     = (const float*)d_in[9];
    const float* theta_w    = (const float*)d_in[10];
    const float* Dv         = (const float*)d_in[11];
    const float* out_proj_w = (const float*)d_in[12];
    float* out = (float*)d_out;

    __nv_bfloat16* p_a3  = sym_addr<__nv_bfloat16>(g_a3);
    __nv_bfloat16* p_yz3 = sym_addr<__nv_bfloat16>(g_yz3);
    __nv_bfloat16* p_w31 = sym_addr<__nv_bfloat16>(g_w31);
    __nv_bfloat16* p_w32 = sym_addr<__nv_bfloat16>(g_w32);

    static bool attr_done = false;
    if (!attr_done) {
        cudaFuncSetAttribute(k_gemm_mma<0>,
            cudaFuncAttributeMaxDynamicSharedMemorySize, GSMEM);
        cudaFuncSetAttribute(k_gemm_mma<1>,
            cudaFuncAttributeMaxDynamicSharedMemorySize, GSMEM);
        attr_done = true;
    }

    // 1. layernorm + hi/lo pack + theta
    k_ln_theta<<<MROWS, 256>>>(u, norm_scale, norm_bias, theta_w);
    // 2. weight transpose + hi/lo pack
    k_tsplit<<<dim3(NPAD1 / 32, DMODEL / 32), dim3(32, 8)>>>(
        in_proj_w, DMODEL, PROJ, p_w31);
    k_tsplit<<<dim3(DMODEL / 32, DINNER / 32), dim3(32, 8)>>>(
        out_proj_w, DINNER, DMODEL, p_w32);
    // 3. proj GEMM (fused epilogue: silu(x), silu(z), tail)
    k_gemm_mma<0><<<dim3(NPAD1 / 128, MROWS / 128), 256, GSMEM>>>(
        p_a3, p_w31, nullptr, nullptr, PROJ, K3_1);
    // 4. tail prep
    k_prep<<<MROWS, 96>>>(A_log, dt_bias, bcB_scale, bcC_scale, B_bias, C_bias);
    // 5. cumsum(phi)
    k_cs_chunk<<<BB * 64, 32>>>();
    k_cs_scan<<<1, 128>>>();
    k_cs_add<<<BB * 64, 256>>>();
    // 6. RoPE
    k_rope<<<MROWS / 8, 256>>>();
    // 7. SSD scan (pipelined)
    k_scan<<<256, 256>>>(Dv);
    // 8. gate + hi/lo pack
    k_mul<<<(MROWS * DINNER) / (256 * 4), 256>>>();
    // 9. out = yz @ out_proj_w + u
    k_gemm_mma<1><<<dim3(DMODEL / 128, MROWS / 128), 256, GSMEM>>>(
        p_yz3, p_w32, u, out, DMODEL, K3_2);
}